// round 13
// baseline (speedup 1.0000x reference)
#include <cuda_runtime.h>

// Lookahead depthwise conv, scatter form + cp.async smem ring + wave-exact
// tiling:  out[t,b,f] = sum_{k=0..20} x[t+k,b,f] * w[f,k],  x[t+k>=S] = 0
// x: (2048, 32, 1024) fp32, w: (1024, 21) fp32, out same shape as x.
//
// R12 residual: grid 1024 tiles over 592 CTA slots (4/SM x 148) = 86.5% slot
// utilization (wave 2 only 73% full). Fix: 1184 tiles = 592*2 exactly.
// 96 lane-chunks x 9 segments (8x228+224) + 32 chunks x 10 segments
// (9x205+203), interleaved so both waves mix tile flavors.

#define S_LEN   2048
#define NBATCH  32
#define NFEAT   1024
#define TAPS    21
#define BF      (NBATCH * NFEAT)      /* 32768 floats per t-slice */
#define PAIRS   (BF / 2)              /* 16384 f32x2 lanes per slice */
#define TPB     128
#define NTILES  1184                  /* = 592 slots x 2 waves exactly */
#define D0      15                    /* cp.async prefetch distance */
#define DSTAGE  16                    /* smem ring stages (power of 2) */
#define RINGB   (DSTAGE * TPB * 8)    /* 16384 bytes per CTA */
#define RMASK   (RINGB - 1)
#define GRP     3                     /* steps per commit group; divides 21 */

typedef unsigned long long u64;

__device__ __forceinline__ u64 ffma2(u64 a, u64 b, u64 c) {
    u64 d;
    asm("fma.rn.f32x2 %0, %1, %2, %3;" : "=l"(d) : "l"(a), "l"(b), "l"(c));
    return d;
}
__device__ __forceinline__ u64 fmul2(u64 a, u64 b) {
    u64 d;
    asm("mul.rn.f32x2 %0, %1, %2;" : "=l"(d) : "l"(a), "l"(b));
    return d;
}
__device__ __forceinline__ u64 pack2(float lo, float hi) {
    u64 d;
    asm("mov.b64 %0, {%1, %2};" : "=l"(d) : "f"(lo), "f"(hi));
    return d;
}
// VOLATILE smem ring load: written asynchronously by cp.async; must not be
// hoisted above cp.async.wait_group.
__device__ __forceinline__ u64 lds64(unsigned a) {
    u64 v;
    asm volatile("ld.shared.b64 %0, [%1];" : "=l"(v) : "r"(a) : "memory");
    return v;
}
__device__ __forceinline__ void stcs64(float* p, u64 v) {
    asm volatile("st.global.cs.b64 [%0], %1;" :: "l"(p), "l"(v) : "memory");
}
#define CP8(dst, src)                                                        \
    asm volatile("cp.async.ca.shared.global [%0], [%1], 8;"                  \
                 :: "r"(dst), "l"(src) : "memory")
// cp.async with runtime src-size (0 => full 8-byte zero-fill, no gmem read).
#define CP8Z(dst, src, sz)                                                   \
    asm volatile("cp.async.ca.shared.global [%0], [%1], 8, %2;"              \
                 :: "r"(dst), "l"(src), "r"(sz) : "memory")
#define CPCOMMIT() asm volatile("cp.async.commit_group;" ::: "memory")
#define CPWAIT(n)  asm volatile("cp.async.wait_group %0;" :: "n"(n) : "memory")

// Uniform scatter step (Rn = literal 0..20 after unroll):
//  - size-guarded cp.async of slice n+D0 (live countdown; <=0 -> zero-fill)
//  - commit+wait once per 3 steps (prologue = 5 groups; wait(4) at n=3j+2
//    guarantees slices through n+3 resident for the next group's ring reads)
//  - k=20 completes oldest acc; store iff 0 <= s_ctr < tseg (window covers
//    steps 20..tseg+19); surplus steps in the last chunk are no-ops
//  - prefetch next slice from ring
#define STEP(Rn)                                                             \
  do {                                                                       \
    const int R_ = (Rn) % TAPS;                                              \
    u64 xv_ = xv_next;                                                       \
    unsigned sz_ = (live > 0) ? 8u : 0u;                                     \
    --live;                                                                  \
    CP8Z(sbase + woff, ldp, sz_);                                            \
    ldp += BF;                                                               \
    woff = (woff + TPB * 8) & RMASK;                                         \
    if (((Rn) % GRP) == GRP - 1) {                                           \
      CPCOMMIT();                                                            \
      CPWAIT(4);                                                             \
    }                                                                        \
    const int DONE_ = (R_ + 1) % TAPS;                                       \
    acc[DONE_] = ffma2(xv_, wk[TAPS - 1], acc[DONE_]);                       \
    if ((unsigned)s_ctr < (unsigned)tseg) {                                  \
      stcs64(stp, acc[DONE_]);                                               \
      stp += BF;                                                             \
    }                                                                        \
    ++s_ctr;                                                                 \
    _Pragma("unroll")                                                        \
    for (int k_ = 1; k_ < TAPS; ++k_)                                        \
      acc[(R_ - k_ + 2 * TAPS) % TAPS] =                                     \
          ffma2(xv_, wk[k_], acc[(R_ - k_ + 2 * TAPS) % TAPS]);              \
    acc[R_] = fmul2(xv_, wk[0]);                                             \
    xv_next = lds64(sbase + roff);                                           \
    roff = (roff + TPB * 8) & RMASK;                                         \
  } while (0)

__global__ void __launch_bounds__(TPB, 4)
lookahead_kernel(const float* __restrict__ x,
                 const float* __restrict__ w,
                 float* __restrict__ out)
{
    __shared__ __align__(16) char ring[RINGB];

    // bid -> (chunk, t0, tseg). Per 4-chunk group: chunks 4g,4g+1,4g+2 carry
    // 9 segments (8x228 + 224); chunk 4g+3 carries 10 (9x205 + 203).
    // 32 groups x 37 tiles = 1184.
    const unsigned g = blockIdx.x / 37u;
    const unsigned r = blockIdx.x % 37u;
    unsigned chunk, t0, tseg;
    if (r < 27u) {
        const unsigned seg = r % 9u;
        chunk = 4u * g + r / 9u;
        t0 = seg * 228u;
        tseg = (seg == 8u) ? 224u : 228u;
    } else {
        const unsigned seg = r - 27u;
        chunk = 4u * g + 3u;
        t0 = seg * 205u;
        tseg = (seg == 9u) ? 203u : 205u;
    }

    const unsigned p = chunk * TPB + threadIdx.x;   // pair id
    const unsigned base = 2u * p;                   // float offset in slice
    const unsigned f0 = base & (NFEAT - 1);

    const unsigned sbase =
        (unsigned)__cvta_generic_to_shared(ring) + threadIdx.x * 8u;

    // Per-thread packed weights: wk[k] = (w[f0][k], w[f0+1][k])
    u64 wk[TAPS];
#pragma unroll
    for (int k = 0; k < TAPS; ++k)
        wk[k] = pack2(w[f0 * TAPS + k], w[(f0 + 1) * TAPS + k]);

    const float* ldp = x + (size_t)t0 * BF + base;
    float*       stp = out + (size_t)t0 * BF + base;

    // Real slices wanted: t0 .. t0+tseg+19, clipped at S_LEN (zeros beyond).
    const int nsteps = (int)tseg + TAPS - 1;
    int live = min(nsteps, (int)(S_LEN - t0)) - D0;   // post-prologue loads

    unsigned woff = 0, roff = 0;

    // Prologue: 15 slices (t0..t0+14; max t0 = 1845 -> 1859 < 2048, always
    // in-bounds) as 5 commit groups of 3.
#pragma unroll
    for (int i = 0; i < D0; ++i) {
        CP8(sbase + woff, ldp);
        if (i % GRP == GRP - 1) CPCOMMIT();
        ldp += BF;
        woff = (woff + TPB * 8) & RMASK;
    }
    CPWAIT(4);                            // group 0 (slices 0-2) complete
    u64 xv_next = lds64(sbase + roff);    // slice 0
    roff = (roff + TPB * 8) & RMASK;

    u64 acc[TAPS];
#pragma unroll
    for (int j = 0; j < TAPS; ++j) acc[j] = 0ull;

    int s_ctr = -(TAPS - 1);              // store window: steps 20..tseg+19

    // K chunks of 21 uniform steps; surplus steps (21K - nsteps) are inert
    // (zero-fill loads, store predicate off, discarded ring reads).
    const int K = (nsteps + TAPS - 1) / TAPS;
    for (int k = 0; k < K; ++k) {
#pragma unroll
        for (int rr = 0; rr < TAPS; ++rr)
            STEP(rr);
    }
}

extern "C" void kernel_launch(void* const* d_in, const int* in_sizes, int n_in,
                              void* d_out, int out_size)
{
    const float* x = (const float*)d_in[0];   // (2048, 32, 1024) fp32
    const float* w = (const float*)d_in[1];   // (1024, 21) fp32
    float* out = (float*)d_out;               // (2048, 32, 1024) fp32

    lookahead_kernel<<<NTILES, TPB>>>(x, w, out);
}

// round 14
// speedup vs baseline: 1.0032x; 1.0032x over previous
#include <cuda_runtime.h>

// Lookahead depthwise conv, scatter + cp.async smem ring + wave-exact tiles:
//   out[t,b,f] = sum_{k=0..20} x[t+k,b,f] * w[f,k],  x[t+k>=S] = 0
// x: (2048, 32, 1024) fp32, w: (1024, 21) fp32, out same shape as x.
//
// 1184 tiles = 592 CTA slots (4/SM x 148) x 2 waves exactly.
// Per 4-chunk group: 3 chunks split 2048 t as 8x228 + 224(boundary),
// 1 chunk as 9x205 + 203(boundary). Interior tiles (87%) run fully static
// code (R12 per-step cost); only boundary tiles pay runtime guards.

#define S_LEN   2048
#define NFEAT   1024
#define TAPS    21
#define BF      32768                 /* floats per t-slice (32*1024) */
#define TPB     128
#define NTILES  1184
#define D0      15                    /* cp.async prefetch distance */
#define DSTAGE  16                    /* smem ring stages */
#define RINGB   (DSTAGE * TPB * 8)    /* 16384 B per CTA */
#define RMASK   (RINGB - 1)
#define GRP     3                     /* steps per commit group */

typedef unsigned long long u64;

__device__ __forceinline__ u64 ffma2(u64 a, u64 b, u64 c) {
    u64 d;
    asm("fma.rn.f32x2 %0, %1, %2, %3;" : "=l"(d) : "l"(a), "l"(b), "l"(c));
    return d;
}
__device__ __forceinline__ u64 fmul2(u64 a, u64 b) {
    u64 d;
    asm("mul.rn.f32x2 %0, %1, %2;" : "=l"(d) : "l"(a), "l"(b));
    return d;
}
__device__ __forceinline__ u64 pack2(float lo, float hi) {
    u64 d;
    asm("mov.b64 %0, {%1, %2};" : "=l"(d) : "f"(lo), "f"(hi));
    return d;
}
// VOLATILE ring load: smem written asynchronously by cp.async; must not be
// hoisted above cp.async.wait_group.
__device__ __forceinline__ u64 lds64(unsigned a) {
    u64 v;
    asm volatile("ld.shared.b64 %0, [%1];" : "=l"(v) : "r"(a) : "memory");
    return v;
}
__device__ __forceinline__ void stcs64(float* p, u64 v) {
    asm volatile("st.global.cs.b64 [%0], %1;" :: "l"(p), "l"(v) : "memory");
}
#define CP8(dst, src)                                                        \
    asm volatile("cp.async.ca.shared.global [%0], [%1], 8;"                  \
                 :: "r"(dst), "l"(src) : "memory")
#define CP8Z(dst, src, sz)                                                   \
    asm volatile("cp.async.ca.shared.global [%0], [%1], 8, %2;"              \
                 :: "r"(dst), "l"(src), "r"(sz) : "memory")
#define CPCOMMIT() asm volatile("cp.async.commit_group;" ::: "memory")
#define CPWAIT(n)  asm volatile("cp.async.wait_group %0;" :: "n"(n) : "memory")

// ---- interior step: ALL flags compile-time, unconditional load ----
#define STEP_I(Rn, DO_STORE, DO_LOAD)                                        \
  do {                                                                       \
    const int R_ = (Rn) % TAPS;                                              \
    u64 xv_ = xv_next;                                                       \
    if (DO_LOAD) {                                                           \
      CP8(sbase + woff, ldp);                                                \
      ldp += BF;                                                             \
      woff = (woff + TPB * 8) & RMASK;                                       \
    }                                                                        \
    if (((Rn) % GRP) == GRP - 1) { CPCOMMIT(); CPWAIT(4); }                  \
    const int DONE_ = (R_ + 1) % TAPS;                                       \
    acc[DONE_] = ffma2(xv_, wk[TAPS - 1], acc[DONE_]);                       \
    if (DO_STORE) {                                                          \
      stcs64(stp, acc[DONE_]);                                               \
      stp += BF;                                                             \
    }                                                                        \
    _Pragma("unroll")                                                        \
    for (int k_ = 1; k_ < TAPS; ++k_)                                        \
      acc[(R_ - k_ + 2 * TAPS) % TAPS] =                                     \
          ffma2(xv_, wk[k_], acc[(R_ - k_ + 2 * TAPS) % TAPS]);              \
    acc[R_] = fmul2(xv_, wk[0]);                                             \
    xv_next = lds64(sbase + roff);                                           \
    roff = (roff + TPB * 8) & RMASK;                                         \
  } while (0)

// ---- boundary step: runtime zero-fill guard + store window (11% of tiles) -
#define STEP_B(Rn)                                                           \
  do {                                                                       \
    const int R_ = (Rn) % TAPS;                                              \
    u64 xv_ = xv_next;                                                       \
    unsigned sz_ = (live > 0) ? 8u : 0u;                                     \
    --live;                                                                  \
    CP8Z(sbase + woff, ldp, sz_);                                            \
    ldp += BF;                                                               \
    woff = (woff + TPB * 8) & RMASK;                                         \
    if (((Rn) % GRP) == GRP - 1) { CPCOMMIT(); CPWAIT(4); }                  \
    const int DONE_ = (R_ + 1) % TAPS;                                       \
    acc[DONE_] = ffma2(xv_, wk[TAPS - 1], acc[DONE_]);                       \
    if ((unsigned)s_ctr < (unsigned)tseg) {                                  \
      stcs64(stp, acc[DONE_]);                                               \
      stp += BF;                                                             \
    }                                                                        \
    ++s_ctr;                                                                 \
    _Pragma("unroll")                                                        \
    for (int k_ = 1; k_ < TAPS; ++k_)                                        \
      acc[(R_ - k_ + 2 * TAPS) % TAPS] =                                     \
          ffma2(xv_, wk[k_], acc[(R_ - k_ + 2 * TAPS) % TAPS]);              \
    acc[R_] = fmul2(xv_, wk[0]);                                             \
    xv_next = lds64(sbase + roff);                                           \
    roff = (roff + TPB * 8) & RMASK;                                         \
  } while (0)

// Shared prologue: 15 unconditional slice loads (always in-bounds: max
// t0 = 1845 -> slice 1859 < 2048) as 5 commit groups of 3, then slice 0.
#define PROLOGUE()                                                           \
    unsigned woff = 0, roff = 0;                                             \
    _Pragma("unroll")                                                        \
    for (int i = 0; i < D0; ++i) {                                           \
        CP8(sbase + woff, ldp);                                              \
        if (i % GRP == GRP - 1) CPCOMMIT();                                  \
        ldp += BF;                                                           \
        woff = (woff + TPB * 8) & RMASK;                                     \
    }                                                                        \
    CPWAIT(4);                                                               \
    u64 xv_next = lds64(sbase + roff);                                       \
    roff = (roff + TPB * 8) & RMASK;                                         \
    u64 acc[TAPS];                                                           \
    _Pragma("unroll")                                                        \
    for (int j_ = 0; j_ < TAPS; ++j_) acc[j_] = 0ull

// Interior tile, fully static. NSTEPS = 21 + NMAINC*21 + NTAILC; loads run
// through step NSTEPS-D0-1: TAILLOADS = NSTEPS-D0 - 21 - NMAINC*21.
template <int NMAINC, int NTAILC, int TAILLOADS>
__device__ __forceinline__ void run_interior(const float* ldp,
                                             float* stp,
                                             const u64* __restrict__ wk,
                                             unsigned sbase)
{
    PROLOGUE();
#pragma unroll
    for (int n = 0; n < TAPS; ++n)
        STEP_I(n, n == TAPS - 1, 1);
    for (int c = 0; c < NMAINC; ++c) {
#pragma unroll
        for (int r = 0; r < TAPS; ++r)
            STEP_I(r, 1, 1);
    }
#pragma unroll
    for (int r = 0; r < NTAILC; ++r)
        STEP_I(r, 1, r < TAILLOADS);
}

// Boundary tile (t0 + tseg == S_LEN): runtime store window + zero-fill of
// the 20 lookahead-pad slices past t=2047. Surplus steps in the last 21-chunk
// are inert (store predicate off, zero-fill loads).
__device__ __forceinline__ void run_boundary(const float* ldp,
                                             float* stp,
                                             const u64* __restrict__ wk,
                                             unsigned sbase,
                                             int tseg, int live)
{
    PROLOGUE();
    int s_ctr = -(TAPS - 1);
    const int K = (tseg + 2 * (TAPS - 1)) / TAPS;   // ceil((tseg+20)/21)
    for (int k = 0; k < K; ++k) {
#pragma unroll
        for (int r = 0; r < TAPS; ++r)
            STEP_B(r);
    }
}

__global__ void __launch_bounds__(TPB, 4)
lookahead_kernel(const float* __restrict__ x,
                 const float* __restrict__ w,
                 float* __restrict__ out)
{
    __shared__ __align__(16) char ring[RINGB];

    // bid -> (chunk, t0, flavor). Per 4-chunk group g: chunks 4g..4g+2 carry
    // 9 tiles each (8 interior-228 + boundary-224); chunk 4g+3 carries 10
    // (9 interior-205 + boundary-203). 32 groups x 37 = 1184 tiles.
    const unsigned g = blockIdx.x / 37u;
    const unsigned r = blockIdx.x % 37u;
    unsigned chunk, t0;
    int kind;                           // 0: int-228, 2: int-205, 1/3: bnd
    if (r < 27u) {
        chunk = 4u * g + r / 9u;
        const unsigned seg = r % 9u;
        t0 = seg * 228u;
        kind = (seg == 8u) ? 1 : 0;     // boundary tseg = 224
    } else {
        chunk = 4u * g + 3u;
        const unsigned seg = r - 27u;
        t0 = seg * 205u;
        kind = (seg == 9u) ? 3 : 2;     // boundary tseg = 203
    }

    const unsigned p = chunk * TPB + threadIdx.x;   // pair id
    const unsigned base = 2u * p;                   // float offset in slice
    const unsigned f0 = base & (NFEAT - 1);

    const unsigned sbase =
        (unsigned)__cvta_generic_to_shared(ring) + threadIdx.x * 8u;

    // Per-thread packed weights: wk[k] = (w[f0][k], w[f0+1][k])
    u64 wk[TAPS];
#pragma unroll
    for (int k = 0; k < TAPS; ++k)
        wk[k] = pack2(w[f0 * TAPS + k], w[(f0 + 1) * TAPS + k]);

    const float* ldp = x + (size_t)t0 * BF + base;
    float*       stp = out + (size_t)t0 * BF + base;

    if (kind == 0) {
        // TSEG=228: NSTEPS=248 = 21 + 10*21 + 17; TAILLOADS = 233-231 = 2.
        run_interior<10, 17, 2>(ldp, stp, wk, sbase);
    } else if (kind == 2) {
        // TSEG=205: NSTEPS=225 = 21 + 9*21 + 15; TAILLOADS = 210-210 = 0.
        run_interior<9, 15, 0>(ldp, stp, wk, sbase);
    } else if (kind == 1) {
        run_boundary(ldp, stp, wk, sbase, 224, (int)(S_LEN - t0) - D0);
    } else {
        run_boundary(ldp, stp, wk, sbase, 203, (int)(S_LEN - t0) - D0);
    }
}

extern "C" void kernel_launch(void* const* d_in, const int* in_sizes, int n_in,
                              void* d_out, int out_size)
{
    const float* x = (const float*)d_in[0];   // (2048, 32, 1024) fp32
    const float* w = (const float*)d_in[1];   // (1024, 21) fp32
    float* out = (float*)d_out;               // (2048, 32, 1024) fp32

    lookahead_kernel<<<NTILES, TPB>>>(x, w, out);
}

// round 15
// speedup vs baseline: 1.0652x; 1.0618x over previous
#include <cuda_runtime.h>

// Lookahead depthwise conv, scatter form + cp.async smem-staged input stream:
//   out[t,b,f] = sum_{k=0..20} x[t+k,b,f] * w[f,k],  x[t+k>=S] = 0
// x: (2048, 32, 1024) fp32, w: (1024, 21) fp32, out same shape as x.
//
// R12 (94.2us, DRAM 69%) with ONE change: pipeline depth doubled
// (D0 15->30, ring 16->32 stages, 32KB smem/CTA) to test whether the
// 5.6 TB/s plateau is congested-latency-bound (helps) or HBM R/W
// turnaround efficiency (flat).

#define S_LEN   2048
#define NBATCH  32
#define NFEAT   1024
#define TAPS    21
#define BF      (NBATCH * NFEAT)      /* 32768 floats per t-slice */
#define PAIRS   (BF / 2)              /* 16384 f32x2 lanes per slice */
#define SPLIT   8
#define TSEG    (S_LEN / SPLIT)       /* 256 outputs per segment */
#define TPB     128
#define CHUNKS  (PAIRS / TPB)         /* 128 lane-chunks */
#define NTILES  (CHUNKS * SPLIT)      /* 1024 = grid size */
#define NSTEPS  (TSEG + TAPS - 1)     /* 276 consumed slices per tile */
#define D0      30                    /* cp.async prefetch distance */
#define DSTAGE  32                    /* smem ring stages (power of 2) */
#define RINGB   (DSTAGE * TPB * 8)    /* 32768 bytes per CTA */
#define RMASK   (RINGB - 1)
#define GRP     3                     /* steps per commit group; divides 21 */
#define WAITN   9                     /* D0/GRP - 1 */
#define NTAIL   3

typedef unsigned long long u64;

__device__ __forceinline__ u64 ffma2(u64 a, u64 b, u64 c) {
    u64 d;
    asm("fma.rn.f32x2 %0, %1, %2, %3;" : "=l"(d) : "l"(a), "l"(b), "l"(c));
    return d;
}
__device__ __forceinline__ u64 fmul2(u64 a, u64 b) {
    u64 d;
    asm("mul.rn.f32x2 %0, %1, %2;" : "=l"(d) : "l"(a), "l"(b));
    return d;
}
__device__ __forceinline__ u64 pack2(float lo, float hi) {
    u64 d;
    asm("mov.b64 %0, {%1, %2};" : "=l"(d) : "f"(lo), "f"(hi));
    return d;
}
// VOLATILE smem ring load: must not be hoisted above cp.async.wait_group
// (the ring is written asynchronously by LDGSTS).
__device__ __forceinline__ u64 lds64(unsigned a) {
    u64 v;
    asm volatile("ld.shared.b64 %0, [%1];" : "=l"(v) : "r"(a) : "memory");
    return v;
}
// Streaming store: out is written once, never re-read -> evict-first.
__device__ __forceinline__ void stcs64(float* p, u64 v) {
    asm volatile("st.global.cs.b64 [%0], %1;" :: "l"(p), "l"(v) : "memory");
}
// cp.async, 8 bytes, unconditional.
#define CP8(dst, src)                                                        \
    asm volatile("cp.async.ca.shared.global [%0], [%1], 8;"                  \
                 :: "r"(dst), "l"(src) : "memory")
// cp.async with runtime src-size (0 => full 8-byte zero-fill, no gmem read).
#define CP8Z(dst, src, sz)                                                   \
    asm volatile("cp.async.ca.shared.global [%0], [%1], 8, %2;"              \
                 :: "r"(dst), "l"(src), "r"(sz) : "memory")
#define CPCOMMIT() asm volatile("cp.async.commit_group;" ::: "memory")
#define CPWAIT(n)  asm volatile("cp.async.wait_group %0;" :: "n"(n) : "memory")

// One scatter step. Rn folds to a literal after unrolling.
// LMODE: 0 = no load, 1 = unconditional load, 2 = size-guarded load.
// Commit + wait on the last step of each 3-step group: with 10 prologue
// groups, wait_group(WAITN=9) at step n=3j+2 guarantees slices through n+3
// resident -- exactly covering the next group's 3 ring reads.
// Ring safety: write (slice n+30) vs pending reads (slices n..275):
// collision class n-2 (mod 32) is already consumed.
#define STEP(Rn, DO_STORE, LMODE)                                            \
  do {                                                                       \
    const int R_ = (Rn) % TAPS;                                              \
    u64 xv_ = xv_next;                                                       \
    if ((LMODE) == 1) {                                                      \
      CP8(sbase + woff, ldp);                                                \
      ldp += BF;                                                             \
      woff = (woff + TPB * 8) & RMASK;                                       \
    } else if ((LMODE) == 2) {                                               \
      unsigned sz_ = (live > 0) ? 8u : 0u;                                   \
      --live;                                                                \
      CP8Z(sbase + woff, ldp, sz_);                                          \
      ldp += BF;                                                             \
      woff = (woff + TPB * 8) & RMASK;                                       \
    }                                                                        \
    if (((Rn) % GRP) == GRP - 1) {                                           \
      CPCOMMIT();                                                            \
      CPWAIT(WAITN);                                                         \
    }                                                                        \
    const int DONE_ = (R_ + 1) % TAPS;                                       \
    acc[DONE_] = ffma2(xv_, wk[TAPS - 1], acc[DONE_]);                       \
    if (DO_STORE) {                                                          \
      stcs64(stp, acc[DONE_]);                                               \
      stp += BF;                                                             \
    }                                                                        \
    _Pragma("unroll")                                                        \
    for (int k_ = 1; k_ < TAPS; ++k_)                                        \
      acc[(R_ - k_ + 2 * TAPS) % TAPS] =                                     \
          ffma2(xv_, wk[k_], acc[(R_ - k_ + 2 * TAPS) % TAPS]);              \
    acc[R_] = fmul2(xv_, wk[0]);                                             \
    xv_next = lds64(sbase + roff);                                           \
    roff = (roff + TPB * 8) & RMASK;                                         \
  } while (0)

template <bool GUARD>
__device__ __forceinline__ void run_segment(const float* __restrict__ xin,
                                            float* __restrict__ stp,
                                            const u64* __restrict__ wk,
                                            int live, unsigned sbase)
{
    const float* ldp = xin;       // next slice to prefetch
    unsigned woff = 0, roff = 0;

    // Prologue: issue D0=30 slices (t0..t0+29; max t0+29 = 1821 < 2048,
    // always in-bounds) as 10 commit groups of 3.
#pragma unroll
    for (int i = 0; i < D0; ++i) {
        CP8(sbase + woff, ldp);
        if (i % GRP == GRP - 1) CPCOMMIT();
        ldp += BF;
        woff = (woff + TPB * 8) & RMASK;
    }
    CPWAIT(WAITN);                        // group 0 (slices 0-2) complete
    u64 xv_next = lds64(sbase + roff);    // slice 0
    roff = (roff + TPB * 8) & RMASK;

    u64 acc[TAPS];
#pragma unroll
    for (int j = 0; j < TAPS; ++j) acc[j] = 0ull;

    if (GUARD) {
        // s=7: every load size-guarded by the t<2048 countdown
        // (live = 226: real slices 30..255, zero-fill beyond).
#pragma unroll
        for (int n = 0; n < TAPS; ++n)
            STEP(n, n == TAPS - 1, 2);
        for (int c = 0; c < 12; ++c) {
#pragma unroll
            for (int r = 0; r < TAPS; ++r)
                STEP(r, true, 2);
        }
    } else {
        // Interior: slices t0+30..t0+260 provably < 2048 -> unconditional.
#pragma unroll
        for (int n = 0; n < TAPS; ++n)
            STEP(n, n == TAPS - 1, 1);
        for (int c = 0; c < 10; ++c) {
#pragma unroll
            for (int r = 0; r < TAPS; ++r)
                STEP(r, true, 1);
        }
        // Chunk 11 (n = 231..251): 15 real loads remain (slices 261..275).
        live = 15;
#pragma unroll
        for (int r = 0; r < TAPS; ++r)
            STEP(r, true, 2);
        // Chunk 12 (n = 252..272): no loads.
#pragma unroll
        for (int r = 0; r < TAPS; ++r)
            STEP(r, true, 0);
    }

    // Tail: n = 273..275; no loads (empty commit group keeps counts aligned).
#pragma unroll
    for (int r = 0; r < NTAIL; ++r)
        STEP(r, true, 0);
}

__global__ void __launch_bounds__(TPB, 4)
lookahead_kernel(const float* __restrict__ x,
                 const float* __restrict__ w,
                 float* __restrict__ out)
{
    __shared__ __align__(16) char ring[RINGB];

    const unsigned c = blockIdx.x & (CHUNKS - 1);   // lane-chunk
    const unsigned s = blockIdx.x >> 7;             // t-segment (CHUNKS=128)
    const unsigned p = c * TPB + threadIdx.x;       // pair id
    const unsigned base = 2u * p;                   // float offset in slice
    const unsigned f0 = base & (NFEAT - 1);

    // Per-thread smem column base (each thread streams its own 8B column).
    const unsigned sbase =
        (unsigned)__cvta_generic_to_shared(ring) + threadIdx.x * 8u;

    // Per-thread packed weights: wk[k] = (w[f0][k], w[f0+1][k])
    u64 wk[TAPS];
#pragma unroll
    for (int k = 0; k < TAPS; ++k)
        wk[k] = pack2(w[f0 * TAPS + k], w[(f0 + 1) * TAPS + k]);

    const unsigned t0 = s * TSEG;
    const float* xin = x + (size_t)t0 * BF + base;
    float* stp = out + (size_t)t0 * BF + base;

    if (s < SPLIT - 1) {
        run_segment<false>(xin, stp, wk, 0, sbase);
    } else {
        // Real loads while slice index i = n + D0 satisfies t0 + i < S_LEN.
        run_segment<true>(xin, stp, wk, (int)(S_LEN - t0) - D0, sbase);
    }
}

extern "C" void kernel_launch(void* const* d_in, const int* in_sizes, int n_in,
                              void* d_out, int out_size)
{
    const float* x = (const float*)d_in[0];   // (2048, 32, 1024) fp32
    const float* w = (const float*)d_in[1];   // (1024, 21) fp32
    float* out = (float*)d_out;               // (2048, 32, 1024) fp32

    lookahead_kernel<<<NTILES, TPB>>>(x, w, out);
}